// round 16
// baseline (speedup 1.0000x reference)
#include <cuda_runtime.h>
#include <cuda_bf16.h>
#include <math.h>
#include <stdint.h>

#define TOKENS 131072
#define CD 120

typedef unsigned long long u64;
typedef __nv_bfloat16 bf16;

__device__ __forceinline__ uint32_t smem_u32(const void* p) {
    uint32_t a;
    asm("{ .reg .u64 t; cvta.to.shared.u64 t, %1; cvt.u32.u64 %0, t; }" : "=r"(a) : "l"(p));
    return a;
}

// pack pair of floats (even, odd) into bf16x2 (first arg -> low half)
__device__ __forceinline__ uint32_t bf16pair(float e, float o) {
    uint32_t hp;
    asm("cvt.rn.bf16x2.f32 %0, %1, %2;" : "=r"(hp) : "f"(o), "f"(e));
    return hp;
}

__device__ __forceinline__ void ldsm4(uint32_t* r, uint32_t addr) {
    asm volatile("ldmatrix.sync.aligned.m8n8.x4.shared.b16 {%0,%1,%2,%3}, [%4];"
                 : "=r"(r[0]), "=r"(r[1]), "=r"(r[2]), "=r"(r[3]) : "r"(addr));
}
__device__ __forceinline__ void ldsm2(uint32_t* r, uint32_t addr) {
    asm volatile("ldmatrix.sync.aligned.m8n8.x2.shared.b16 {%0,%1}, [%2];"
                 : "=r"(r[0]), "=r"(r[1]) : "r"(addr));
}
__device__ __forceinline__ void ldsm2_trans(uint32_t* r, uint32_t addr) {
    asm volatile("ldmatrix.sync.aligned.m8n8.x2.trans.shared.b16 {%0,%1}, [%2];"
                 : "=r"(r[0]), "=r"(r[1]) : "r"(addr));
}
__device__ __forceinline__ void mma_bf16(float* c, const uint32_t* a, const uint32_t* b) {
    asm volatile(
        "mma.sync.aligned.m16n8k16.row.col.f32.bf16.bf16.f32 "
        "{%0,%1,%2,%3},{%4,%5,%6,%7},{%8,%9},{%0,%1,%2,%3};"
        : "+f"(c[0]), "+f"(c[1]), "+f"(c[2]), "+f"(c[3])
        : "r"(a[0]), "r"(a[1]), "r"(a[2]), "r"(a[3]), "r"(b[0]), "r"(b[1]));
}
__device__ __forceinline__ void cp16(uint32_t dst, const void* src) {
    asm volatile("cp.async.cg.shared.global [%0], [%1], 16;" :: "r"(dst), "l"(src));
}
__device__ __forceinline__ void zero16(uint32_t dst) {
    asm volatile("st.shared.v4.b32 [%0], {%1,%1,%1,%1};" :: "r"(dst), "r"(0u));
}

// -------- scratch (device globals; aliased by lifetime) --------
__device__ float g_bufA[131072 * 720];       // qkv bf16 head-major planes -> later mlp pre-act
__device__ float g_xres[131072 * 120];       // residual after proj
__device__ bf16  g_ln_hi[131072 * 120];      // LN1 out -> later LN2 out
__device__ bf16  g_at_hi[131072 * 240];      // attn out -> later gated hid
__device__ bf16  g_w_hi[201600];             // weights bf16 (mlp region interleaved)
__device__ float g_bias[1200];               // [0,720) qkv, [720,1200) mlp interleaved

// ---------------- weight/bias prep ----------------
__global__ void prep_weights(const float* w_qs, const float* w_qm, const float* w_pj,
                             const float* w_f1, const float* w_f2, const float* w_c2,
                             const float* b_qs, const float* b_qm,
                             const float* b_f1, const float* b_f2)
{
    int i = blockIdx.x * blockDim.x + threadIdx.x;
    if (i < 201600) {
        const float* src; int off, dst;
        if (i < 43200)       { src = w_qs; off = i; dst = i; }
        else if (i < 86400)  { src = w_qm; off = i - 43200; dst = i; }
        else if (i < 115200) { src = w_pj; off = i - 86400; dst = i; }
        else if (i < 144000) {
            src = w_f1; off = i - 115200;
            int r = off / 120, c = off % 120;
            dst = 115200 + (2 * r) * 120 + c;       // fc11 -> even rows
        } else if (i < 172800) {
            src = w_f2; off = i - 144000;
            int r = off / 120, c = off % 120;
            dst = 115200 + (2 * r + 1) * 120 + c;   // fc12 -> odd rows
        } else { src = w_c2; off = i - 172800; dst = i; }
        g_w_hi[dst] = __float2bfloat16(src[off]);
    } else if (i < 201600 + 1200) {
        int j = i - 201600;
        if (j < 360)       g_bias[j] = b_qs[j];
        else if (j < 720)  g_bias[j] = b_qm[j - 360];
        else if (j < 960)  g_bias[720 + 2 * (j - 720)] = b_f1[j - 720];
        else               g_bias[720 + 2 * (j - 960) + 1] = b_f2[j - 960];
    }
}

// ---------------- LayerNorm -> bf16 (+ optional partition) ----------------
__global__ void ln_kernel(const float* __restrict__ x, const float* __restrict__ w,
                          const float* __restrict__ b, bf16* __restrict__ ohi,
                          int partition)
{
    int warp = (blockIdx.x * blockDim.x + threadIdx.x) >> 5;
    int lane = threadIdx.x & 31;
    if (warp >= TOKENS) return;
    const float* xi = x + (size_t)warp * CD;
    float2 v0 = *(const float2*)(xi + 2 * lane);
    float2 v1 = make_float2(0.f, 0.f);
    if (lane < 28) v1 = *(const float2*)(xi + 64 + 2 * lane);
    float s = v0.x + v0.y + v1.x + v1.y;
#pragma unroll
    for (int o = 16; o > 0; o >>= 1) s += __shfl_xor_sync(0xffffffffu, s, o);
    float mean = s * (1.f / 120.f);
    float d0 = v0.x - mean, d1 = v0.y - mean;
    float d2 = (lane < 28) ? v1.x - mean : 0.f, d3 = (lane < 28) ? v1.y - mean : 0.f;
    float s2 = d0 * d0 + d1 * d1 + d2 * d2 + d3 * d3;
#pragma unroll
    for (int o = 16; o > 0; o >>= 1) s2 += __shfl_xor_sync(0xffffffffu, s2, o);
    float rstd = rsqrtf(s2 * (1.f / 120.f) + 1e-5f);

    int outrow = warp;
    if (partition) {
        int g = warp;
        int ww = g & 63, hh = (g >> 6) & 63, dd = (g >> 12) & 3, nn = g >> 14;
        int bwin = (((nn >> 1) * 2 + (dd >> 1)) * 8 + (hh >> 3)) * 8 + (ww >> 3);
        int t = (((nn & 1) * 2 + (dd & 1)) * 8 + (hh & 7)) * 8 + (ww & 7);
        outrow = bwin * 256 + t;
    }
    size_t ob = (size_t)outrow * CD;
    {
        float2 wv = *(const float2*)(w + 2 * lane);
        float2 bv = *(const float2*)(b + 2 * lane);
        *(uint32_t*)(ohi + ob + 2 * lane) =
            bf16pair(d0 * rstd * wv.x + bv.x, d1 * rstd * wv.y + bv.y);
    }
    if (lane < 28) {
        float2 wv = *(const float2*)(w + 64 + 2 * lane);
        float2 bv = *(const float2*)(b + 64 + 2 * lane);
        *(uint32_t*)(ohi + ob + 64 + 2 * lane) =
            bf16pair(d2 * rstd * wv.x + bv.x, d3 * rstd * wv.y + bv.y);
    }
}

// ---------------- tensor-core GEMM: C = A[M,K] @ W[N,K]^T + bias ----------------
// EPI 0: fp32 store; EPI 1: window-reverse + residual; EPI 2: residual add;
// EPI 3: GEGLU gate fused -> bf16 [M,240];
// EPI 4: qkv -> bf16 head-major planes, Q pre-scaled. plane=(sec*3+part)*6+h, [M,20] each.
#define SMB 34816
#define GEMM_SMEM (2 * SMB)

template <int EPI>
__global__ void __launch_bounds__(256, 2) mma_gemm(
    const bf16* __restrict__ Ahi, const bf16* __restrict__ Whi,
    const float* __restrict__ bias, float* __restrict__ Cout,
    const float* __restrict__ resid,
    int N, int K, int ldo, int col_off)
{
    extern __shared__ char dsm[];
    uint32_t sm = smem_u32(dsm);
    int tid = threadIdx.x;
    int lane = tid & 31, wid = tid >> 5;
    int wm = wid & 1, wn = wid >> 1;
    int row0 = blockIdx.x * 128;
    int n0 = blockIdx.y * 128;

    float c[4][4][4];
#pragma unroll
    for (int i = 0; i < 4; i++)
#pragma unroll
        for (int j = 0; j < 4; j++)
#pragma unroll
            for (int q = 0; q < 4; q++) c[i][j][q] = 0.f;

    int panels = K / 120;
    uint32_t aAddr = sm + (uint32_t)((wm * 64 + (lane & 15)) * 272 + ((lane >> 4) << 3) * 2);
    uint32_t bAddr = sm + SMB + (uint32_t)((wn * 32 + (lane & 7)) * 272 + (lane & 8) * 2);

    for (int pan = 0; pan < panels; pan++) {
        int k0e = pan * 120;
        for (int cidx = tid; cidx < 4096; cidx += 256) {
            int buf = cidx >> 11;
            int row = (cidx >> 4) & 127;
            int ch = cidx & 15;
            uint32_t dst = sm + (uint32_t)buf * SMB + (uint32_t)(row * 272 + ch * 16);
            if (ch == 15) { zero16(dst); continue; }
            if (buf == 0) {
                cp16(dst, Ahi + (size_t)(row0 + row) * K + k0e + ch * 8);
            } else {
                int n = n0 + row;
                if (n < N) cp16(dst, Whi + (size_t)n * K + k0e + ch * 8);
                else zero16(dst);
            }
        }
        asm volatile("cp.async.commit_group;" ::: "memory");
        asm volatile("cp.async.wait_group 0;" ::: "memory");
        __syncthreads();

#pragma unroll
        for (int ks = 0; ks < 8; ks++) {
            uint32_t ahi[4][4], bhi[4][2];
#pragma unroll
            for (int nf = 0; nf < 4; nf++)
                ldsm2(bhi[nf], bAddr + (uint32_t)(nf * 8 * 272 + ks * 32));
#pragma unroll
            for (int mf = 0; mf < 4; mf++)
                ldsm4(ahi[mf], aAddr + (uint32_t)(mf * 16 * 272 + ks * 32));
#pragma unroll
            for (int mf = 0; mf < 4; mf++)
#pragma unroll
                for (int nf = 0; nf < 4; nf++) mma_bf16(c[mf][nf], ahi[mf], bhi[nf]);
        }
        if (pan + 1 < panels) __syncthreads();
    }

#pragma unroll
    for (int mf = 0; mf < 4; mf++) {
        int row = row0 + wm * 64 + mf * 16 + (lane >> 2);
#pragma unroll
        for (int half = 0; half < 2; half++) {
            int r = row + half * 8;
            size_t obase = 0;
            const float* rbase = nullptr;
            if (EPI == 1) {
                int bwin = r >> 8, tt = r & 255;
                int ww = bwin & 7, wh = (bwin >> 3) & 7, wd = (bwin >> 6) & 1, wnn = bwin >> 7;
                int iw = tt & 7, ih = (tt >> 3) & 7, id = (tt >> 6) & 1, inn = tt >> 7;
                int n_ = wnn * 2 + inn, d_ = wd * 2 + id, h_ = wh * 8 + ih, w_ = ww * 8 + iw;
                int gidx = ((n_ * 4 + d_) * 64 + h_) * 64 + w_;
                obase = (size_t)gidx * 120;
                rbase = resid + obase;
            } else if (EPI == 0 || EPI == 2) {
                obase = (size_t)r * ldo;
                if (EPI == 2) rbase = resid + obase;
            }
#pragma unroll
            for (int nf = 0; nf < 4; nf++) {
                int col = n0 + wn * 32 + nf * 8 + (lane & 3) * 2;
                if (col >= N) continue;
                float2 bv = *(const float2*)&bias[col];
                float vx = c[mf][nf][half * 2 + 0] + bv.x;
                float vy = c[mf][nf][half * 2 + 1] + bv.y;
                if (EPI == 0) {
                    float2 v = {vx, vy};
                    *(float2*)&Cout[obase + col_off + col] = v;
                } else if (EPI == 3) {
                    float ge = 0.5f * vx * (1.f + erff(vx * 0.70710678118654752f));
                    ((bf16*)Cout)[(size_t)r * 240 + (col >> 1)] = __float2bfloat16(ge * vy);
                } else if (EPI == 4) {
                    int sec = (col >= 360) ? 1 : 0;
                    int rem = col - sec * 360;
                    int part = rem / 120;
                    int within = rem % 120;
                    int hh = within / 20, cc = within % 20;
                    float qsc = (part == 0) ? 0.22360679774997896f : 1.f;
                    size_t dst = ((size_t)((sec * 3 + part) * 6 + hh)) * (TOKENS * 20)
                               + (size_t)r * 20 + cc;
                    *(uint32_t*)((bf16*)Cout + dst) = bf16pair(vx * qsc, vy * qsc);
                } else {
                    float2 rv = *(const float2*)&rbase[col];
                    float2 v = {rv.x + vx, rv.y + vy};
                    *(float2*)&Cout[obase + col] = v;
                }
            }
        }
    }
}

// ---------------- HMMA attention (self+mutual in one launch via blockIdx.z) ----------------
// qkv in head-major planes [36][M][20] bf16: plane=(sec*3+part)*6+h. Staging fully coalesced.
// z=0: self (all 256 keys, out cols 120+h*20)
// z=1: mutual: warps 0-3 = q1 vs k2/v2 (kb 2-3), warps 4-7 = q2 vs k1/v1 (kb 0-1);
//      out row = qrow^128, out cols h*20.
#define ATTN_SMEM 61440

__global__ void __launch_bounds__(256, 2) attn_mma(
    const bf16* __restrict__ qkv, bf16* __restrict__ ohi)
{
    extern __shared__ char asmem[];
    uint32_t sbase = smem_u32(asmem);
    uint32_t Kbase = sbase + 20480;
    uint32_t Vbase = sbase + 40960;
    int h = blockIdx.y;
    int mutual = blockIdx.z;
    int base = blockIdx.x * 256;
    int tid = threadIdx.x;
    int lane = tid & 31, wid = tid >> 5;

    // zero full smem (pad cols 20..31 of every row must be 0)
    for (uint32_t off = (uint32_t)tid * 16; off < 61440; off += 256 * 16)
        zero16(sbase + off);
    __syncthreads();

    // coalesced staging: each plane slice [base..base+256) x 20 bf16 is contiguous (2560 u32)
    const uint32_t* Q32 = (const uint32_t*)(qkv + ((size_t)(mutual * 18 + h)) * (TOKENS * 20) + (size_t)base * 20);
    const uint32_t* K32 = (const uint32_t*)(qkv + ((size_t)(mutual * 18 + 6 + h)) * (TOKENS * 20) + (size_t)base * 20);
    const uint32_t* V32 = (const uint32_t*)(qkv + ((size_t)(mutual * 18 + 12 + h)) * (TOKENS * 20) + (size_t)base * 20);
#pragma unroll
    for (int idx = tid; idx < 2560; idx += 256) {
        int row = idx / 10, cp = idx % 10;
        uint32_t off = (uint32_t)(row * 80 + cp * 4);
        *(uint32_t*)(asmem + off) = Q32[idx];
        *(uint32_t*)(asmem + 20480 + off) = K32[idx];
        *(uint32_t*)(asmem + 40960 + off) = V32[idx];
    }
    __syncthreads();

    // Q fragments (loop-invariant)
    uint32_t aQ = sbase + (uint32_t)((wid * 32 + (lane & 15)) * 80 + ((lane >> 4) << 4));
    uint32_t aq[2][2][4];
#pragma unroll
    for (int mf = 0; mf < 2; mf++)
#pragma unroll
        for (int ks = 0; ks < 2; ks++)
            ldsm4(aq[mf][ks], aQ + (uint32_t)(mf * 16 * 80 + ks * 32));

    uint32_t aK = Kbase + (uint32_t)((lane & 7) * 80 + (lane & 8) * 2);
    uint32_t aV = Vbase + (uint32_t)((lane & 15) * 80);

    float l[4], o[2][3][4];
#pragma unroll
    for (int s = 0; s < 4; s++) l[s] = 0.f;
#pragma unroll
    for (int mf = 0; mf < 2; mf++)
#pragma unroll
        for (int nf = 0; nf < 3; nf++)
#pragma unroll
            for (int q = 0; q < 4; q++) o[mf][nf][q] = 0.f;

    int kb0 = mutual ? ((wid < 4) ? 2 : 0) : 0;
    int nkb = mutual ? 2 : 4;

    for (int kbi = 0; kbi < nkb; kbi++) {
        int kb = kb0 + kbi;
        float c[2][8][4];
#pragma unroll
        for (int mf = 0; mf < 2; mf++)
#pragma unroll
            for (int nf = 0; nf < 8; nf++)
#pragma unroll
                for (int q = 0; q < 4; q++) c[mf][nf][q] = 0.f;

        // S = Q K^T for 64 keys
#pragma unroll
        for (int nf = 0; nf < 8; nf++) {
            uint32_t b0[2], b1[2];
            uint32_t ka = aK + (uint32_t)((kb * 64 + nf * 8) * 80);
            ldsm2(b0, ka);
            ldsm2(b1, ka + 32);
#pragma unroll
            for (int mf = 0; mf < 2; mf++) {
                mma_bf16(c[mf][nf], aq[mf][0], b0);
                mma_bf16(c[mf][nf], aq[mf][1], b1);
            }
        }
        // exp (scores are small: no max subtraction needed) + row-sum
#pragma unroll
        for (int mf = 0; mf < 2; mf++)
#pragma unroll
            for (int hi = 0; hi < 2; hi++) {
                int s = mf * 2 + hi;
                float ls = 0.f;
#pragma unroll
                for (int nf = 0; nf < 8; nf++) {
                    float p0 = __expf(c[mf][nf][hi * 2]);
                    float p1 = __expf(c[mf][nf][hi * 2 + 1]);
                    c[mf][nf][hi * 2] = p0; c[mf][nf][hi * 2 + 1] = p1;
                    ls += p0 + p1;
                }
                ls += __shfl_xor_sync(0xffffffffu, ls, 1);
                ls += __shfl_xor_sync(0xffffffffu, ls, 2);
                l[s] += ls;
            }
        // PV: P(32x64) * V(64x24), V B-fragments via trans-ldmatrix
#pragma unroll
        for (int ks = 0; ks < 4; ks++) {
            uint32_t a[2][4];
#pragma unroll
            for (int mf = 0; mf < 2; mf++) {
                a[mf][0] = bf16pair(c[mf][2 * ks][0],     c[mf][2 * ks][1]);
                a[mf][1] = bf16pair(c[mf][2 * ks][2],     c[mf][2 * ks][3]);
                a[mf][2] = bf16pair(c[mf][2 * ks + 1][0], c[mf][2 * ks + 1][1]);
                a[mf][3] = bf16pair(c[mf][2 * ks + 1][2], c[mf][2 * ks + 1][3]);
            }
            uint32_t vrow = aV + (uint32_t)((kb * 64 + ks * 16) * 80);
#pragma unroll
            for (int nf = 0; nf < 3; nf++) {
                uint32_t vb[2];
                ldsm2_trans(vb, vrow + (uint32_t)(nf * 16));
#pragma unroll
                for (int mf = 0; mf < 2; mf++)
                    mma_bf16(o[mf][nf], a[mf], vb);
            }
        }
    }
    // normalize + write bf16 (cols 20-23 are pad)
    int colbase = mutual ? h * 20 : 120 + h * 20;
#pragma unroll
    for (int mf = 0; mf < 2; mf++)
#pragma unroll
        for (int hi = 0; hi < 2; hi++) {
            int s = mf * 2 + hi;
            float inv = 1.f / l[s];
            int qrow = wid * 32 + mf * 16 + (lane >> 2) + hi * 8;
            int orow = mutual ? (qrow ^ 128) : qrow;
            size_t ob = (size_t)(base + orow) * 240 + colbase;
#pragma unroll
            for (int nf = 0; nf < 3; nf++) {
                int col = nf * 8 + (lane & 3) * 2;
                if (col < 20) {
                    *(uint32_t*)(ohi + ob + col) =
                        bf16pair(o[mf][nf][hi * 2] * inv, o[mf][nf][hi * 2 + 1] * inv);
                }
            }
        }
}

extern "C" void kernel_launch(void* const* d_in, const int* in_sizes, int n_in,
                              void* d_out, int out_size)
{
    const float* x          = (const float*)d_in[0];
    const float* norm1_w    = (const float*)d_in[1];
    const float* norm1_b    = (const float*)d_in[2];
    const float* qkv_self_w = (const float*)d_in[3];
    const float* qkv_self_b = (const float*)d_in[4];
    const float* qkv_mut_w  = (const float*)d_in[5];
    const float* qkv_mut_b  = (const float*)d_in[6];
    const float* proj_w     = (const float*)d_in[7];
    const float* proj_b     = (const float*)d_in[8];
    const float* norm2_w    = (const float*)d_in[9];
    const float* norm2_b    = (const float*)d_in[10];
    const float* fc11_w     = (const float*)d_in[11];
    const float* fc11_b     = (const float*)d_in[12];
    const float* fc12_w     = (const float*)d_in[13];
    const float* fc12_b     = (const float*)d_in[14];
    const float* fc2_w      = (const float*)d_in[15];
    const float* fc2_b      = (const float*)d_in[16];

    float *bufA, *xres, *biasp;
    bf16 *lnhi, *athi, *whi;
    cudaGetSymbolAddress((void**)&bufA, g_bufA);
    cudaGetSymbolAddress((void**)&xres, g_xres);
    cudaGetSymbolAddress((void**)&lnhi, g_ln_hi);
    cudaGetSymbolAddress((void**)&athi, g_at_hi);
    cudaGetSymbolAddress((void**)&whi, g_w_hi);
    cudaGetSymbolAddress((void**)&biasp, g_bias);

    cudaFuncSetAttribute(mma_gemm<1>, cudaFuncAttributeMaxDynamicSharedMemorySize, GEMM_SMEM);
    cudaFuncSetAttribute(mma_gemm<2>, cudaFuncAttributeMaxDynamicSharedMemorySize, GEMM_SMEM);
    cudaFuncSetAttribute(mma_gemm<3>, cudaFuncAttributeMaxDynamicSharedMemorySize, GEMM_SMEM);
    cudaFuncSetAttribute(mma_gemm<4>, cudaFuncAttributeMaxDynamicSharedMemorySize, GEMM_SMEM);
    cudaFuncSetAttribute(attn_mma, cudaFuncAttributeMaxDynamicSharedMemorySize, ATTN_SMEM);

    const int M = TOKENS;
    const int MT = M / 128;

    // 0) weight/bias prep (mlp rows interleaved for gate fusion)
    prep_weights<<<(201600 + 1200 + 255) / 256, 256>>>(
        qkv_self_w, qkv_mut_w, proj_w, fc11_w, fc12_w, fc2_w,
        qkv_self_b, qkv_mut_b, fc11_b, fc12_b);

    // 1) LN1 + window partition -> bf16
    ln_kernel<<<M / 8, 256>>>(x, norm1_w, norm1_b, lnhi, 1);

    // 2) combined qkv GEMM (N=720) -> bufA as bf16 head-major planes, Q pre-scaled
    mma_gemm<4><<<dim3(MT, 6), 256, GEMM_SMEM>>>(lnhi, whi, biasp, bufA, nullptr, 720, 120, 720, 0);

    // 3) attention (self z=0, mutual z=1) -> athi bf16 [M,240]
    attn_mma<<<dim3(512, 6, 2), 256, ATTN_SMEM>>>((const bf16*)bufA, athi);

    // 4) proj GEMM + window reverse + residual -> xres
    mma_gemm<1><<<dim3(MT, 1), 256, GEMM_SMEM>>>(athi, whi + 86400, proj_b, xres, x, 120, 240, 120, 0);

    // 5) LN2 -> bf16
    ln_kernel<<<M / 8, 256>>>(xres, norm2_w, norm2_b, lnhi, 0);

    // 6) MLP GEMM with fused GEGLU (N=480 interleaved) -> athi bf16 [M,240]
    mma_gemm<3><<<dim3(MT, 4), 256, GEMM_SMEM>>>(lnhi, whi + 115200, biasp + 720,
                                                 (float*)athi, nullptr, 480, 120, 240, 0);

    // 7) fc2 GEMM + residual -> d_out
    mma_gemm<2><<<dim3(MT, 1), 256, GEMM_SMEM>>>(athi, whi + 172800, fc2_b, (float*)d_out, xres, 120, 240, 120, 0);
}

// round 17
// speedup vs baseline: 1.6291x; 1.6291x over previous
#include <cuda_runtime.h>
#include <cuda_bf16.h>
#include <math.h>
#include <stdint.h>

#define TOKENS 131072
#define CD 120

typedef unsigned long long u64;
typedef __nv_bfloat16 bf16;

__device__ __forceinline__ uint32_t smem_u32(const void* p) {
    uint32_t a;
    asm("{ .reg .u64 t; cvta.to.shared.u64 t, %1; cvt.u32.u64 %0, t; }" : "=r"(a) : "l"(p));
    return a;
}

// pack pair of floats (even, odd) into bf16x2 (first arg -> low half)
__device__ __forceinline__ uint32_t bf16pair(float e, float o) {
    uint32_t hp;
    asm("cvt.rn.bf16x2.f32 %0, %1, %2;" : "=r"(hp) : "f"(o), "f"(e));
    return hp;
}

__device__ __forceinline__ void ldsm4(uint32_t* r, uint32_t addr) {
    asm volatile("ldmatrix.sync.aligned.m8n8.x4.shared.b16 {%0,%1,%2,%3}, [%4];"
                 : "=r"(r[0]), "=r"(r[1]), "=r"(r[2]), "=r"(r[3]) : "r"(addr));
}
__device__ __forceinline__ void ldsm2(uint32_t* r, uint32_t addr) {
    asm volatile("ldmatrix.sync.aligned.m8n8.x2.shared.b16 {%0,%1}, [%2];"
                 : "=r"(r[0]), "=r"(r[1]) : "r"(addr));
}
__device__ __forceinline__ void ldsm2_trans(uint32_t* r, uint32_t addr) {
    asm volatile("ldmatrix.sync.aligned.m8n8.x2.trans.shared.b16 {%0,%1}, [%2];"
                 : "=r"(r[0]), "=r"(r[1]) : "r"(addr));
}
__device__ __forceinline__ void mma_bf16(float* c, const uint32_t* a, const uint32_t* b) {
    asm volatile(
        "mma.sync.aligned.m16n8k16.row.col.f32.bf16.bf16.f32 "
        "{%0,%1,%2,%3},{%4,%5,%6,%7},{%8,%9},{%0,%1,%2,%3};"
        : "+f"(c[0]), "+f"(c[1]), "+f"(c[2]), "+f"(c[3])
        : "r"(a[0]), "r"(a[1]), "r"(a[2]), "r"(a[3]), "r"(b[0]), "r"(b[1]));
}
__device__ __forceinline__ void cp16(uint32_t dst, const void* src) {
    asm volatile("cp.async.cg.shared.global [%0], [%1], 16;" :: "r"(dst), "l"(src));
}
__device__ __forceinline__ void zero16(uint32_t dst) {
    asm volatile("st.shared.v4.b32 [%0], {%1,%1,%1,%1};" :: "r"(dst), "r"(0u));
}

// -------- scratch (device globals; aliased by lifetime) --------
__device__ float g_bufA[131072 * 720];       // qkv bf16 head-major planes -> later mlp pre-act
__device__ float g_xres[131072 * 120];       // residual after proj
__device__ bf16  g_ln_hi[131072 * 120];      // LN1 out -> later LN2 out
__device__ bf16  g_at_hi[131072 * 240];      // attn out -> later gated hid
__device__ bf16  g_w_hi[201600];             // weights bf16 (mlp region interleaved)
__device__ float g_bias[1200];               // [0,720) qkv, [720,1200) mlp interleaved

// ---------------- weight/bias prep ----------------
__global__ void prep_weights(const float* w_qs, const float* w_qm, const float* w_pj,
                             const float* w_f1, const float* w_f2, const float* w_c2,
                             const float* b_qs, const float* b_qm,
                             const float* b_f1, const float* b_f2)
{
    int i = blockIdx.x * blockDim.x + threadIdx.x;
    if (i < 201600) {
        const float* src; int off, dst;
        if (i < 43200)       { src = w_qs; off = i; dst = i; }
        else if (i < 86400)  { src = w_qm; off = i - 43200; dst = i; }
        else if (i < 115200) { src = w_pj; off = i - 86400; dst = i; }
        else if (i < 144000) {
            src = w_f1; off = i - 115200;
            int r = off / 120, c = off % 120;
            dst = 115200 + (2 * r) * 120 + c;       // fc11 -> even rows
        } else if (i < 172800) {
            src = w_f2; off = i - 144000;
            int r = off / 120, c = off % 120;
            dst = 115200 + (2 * r + 1) * 120 + c;   // fc12 -> odd rows
        } else { src = w_c2; off = i - 172800; dst = i; }
        g_w_hi[dst] = __float2bfloat16(src[off]);
    } else if (i < 201600 + 1200) {
        int j = i - 201600;
        if (j < 360)       g_bias[j] = b_qs[j];
        else if (j < 720)  g_bias[j] = b_qm[j - 360];
        else if (j < 960)  g_bias[720 + 2 * (j - 720)] = b_f1[j - 720];
        else               g_bias[720 + 2 * (j - 960) + 1] = b_f2[j - 960];
    }
}

// ---------------- LayerNorm -> bf16 (+ optional partition) ----------------
__global__ void ln_kernel(const float* __restrict__ x, const float* __restrict__ w,
                          const float* __restrict__ b, bf16* __restrict__ ohi,
                          int partition)
{
    int warp = (blockIdx.x * blockDim.x + threadIdx.x) >> 5;
    int lane = threadIdx.x & 31;
    if (warp >= TOKENS) return;
    const float* xi = x + (size_t)warp * CD;
    float2 v0 = *(const float2*)(xi + 2 * lane);
    float2 v1 = make_float2(0.f, 0.f);
    if (lane < 28) v1 = *(const float2*)(xi + 64 + 2 * lane);
    float s = v0.x + v0.y + v1.x + v1.y;
#pragma unroll
    for (int o = 16; o > 0; o >>= 1) s += __shfl_xor_sync(0xffffffffu, s, o);
    float mean = s * (1.f / 120.f);
    float d0 = v0.x - mean, d1 = v0.y - mean;
    float d2 = (lane < 28) ? v1.x - mean : 0.f, d3 = (lane < 28) ? v1.y - mean : 0.f;
    float s2 = d0 * d0 + d1 * d1 + d2 * d2 + d3 * d3;
#pragma unroll
    for (int o = 16; o > 0; o >>= 1) s2 += __shfl_xor_sync(0xffffffffu, s2, o);
    float rstd = rsqrtf(s2 * (1.f / 120.f) + 1e-5f);

    int outrow = warp;
    if (partition) {
        int g = warp;
        int ww = g & 63, hh = (g >> 6) & 63, dd = (g >> 12) & 3, nn = g >> 14;
        int bwin = (((nn >> 1) * 2 + (dd >> 1)) * 8 + (hh >> 3)) * 8 + (ww >> 3);
        int t = (((nn & 1) * 2 + (dd & 1)) * 8 + (hh & 7)) * 8 + (ww & 7);
        outrow = bwin * 256 + t;
    }
    size_t ob = (size_t)outrow * CD;
    {
        float2 wv = *(const float2*)(w + 2 * lane);
        float2 bv = *(const float2*)(b + 2 * lane);
        *(uint32_t*)(ohi + ob + 2 * lane) =
            bf16pair(d0 * rstd * wv.x + bv.x, d1 * rstd * wv.y + bv.y);
    }
    if (lane < 28) {
        float2 wv = *(const float2*)(w + 64 + 2 * lane);
        float2 bv = *(const float2*)(b + 64 + 2 * lane);
        *(uint32_t*)(ohi + ob + 64 + 2 * lane) =
            bf16pair(d2 * rstd * wv.x + bv.x, d3 * rstd * wv.y + bv.y);
    }
}

// ---------------- tensor-core GEMM: C = A[M,K] @ W[N,K]^T + bias ----------------
// EPI 0: fp32 store; EPI 1: window-reverse + residual; EPI 2: residual add;
// EPI 3: GEGLU gate fused -> bf16 [M,240];
// EPI 4: qkv -> bf16 head-major planes, Q pre-scaled. plane=(sec*3+part)*6+h, [M,20] each.
//        (plane pointers hoisted out of the store loops)
#define SMB 34816
#define GEMM_SMEM (2 * SMB)

template <int EPI>
__global__ void __launch_bounds__(256, 2) mma_gemm(
    const bf16* __restrict__ Ahi, const bf16* __restrict__ Whi,
    const float* __restrict__ bias, float* __restrict__ Cout,
    const float* __restrict__ resid,
    int N, int K, int ldo, int col_off)
{
    extern __shared__ char dsm[];
    uint32_t sm = smem_u32(dsm);
    int tid = threadIdx.x;
    int lane = tid & 31, wid = tid >> 5;
    int wm = wid & 1, wn = wid >> 1;
    int row0 = blockIdx.x * 128;
    int n0 = blockIdx.y * 128;

    float c[4][4][4];
#pragma unroll
    for (int i = 0; i < 4; i++)
#pragma unroll
        for (int j = 0; j < 4; j++)
#pragma unroll
            for (int q = 0; q < 4; q++) c[i][j][q] = 0.f;

    int panels = K / 120;
    uint32_t aAddr = sm + (uint32_t)((wm * 64 + (lane & 15)) * 272 + ((lane >> 4) << 3) * 2);
    uint32_t bAddr = sm + SMB + (uint32_t)((wn * 32 + (lane & 7)) * 272 + (lane & 8) * 2);

    for (int pan = 0; pan < panels; pan++) {
        int k0e = pan * 120;
        for (int cidx = tid; cidx < 4096; cidx += 256) {
            int buf = cidx >> 11;
            int row = (cidx >> 4) & 127;
            int ch = cidx & 15;
            uint32_t dst = sm + (uint32_t)buf * SMB + (uint32_t)(row * 272 + ch * 16);
            if (ch == 15) { zero16(dst); continue; }
            if (buf == 0) {
                cp16(dst, Ahi + (size_t)(row0 + row) * K + k0e + ch * 8);
            } else {
                int n = n0 + row;
                if (n < N) cp16(dst, Whi + (size_t)n * K + k0e + ch * 8);
                else zero16(dst);
            }
        }
        asm volatile("cp.async.commit_group;" ::: "memory");
        asm volatile("cp.async.wait_group 0;" ::: "memory");
        __syncthreads();

#pragma unroll
        for (int ks = 0; ks < 8; ks++) {
            uint32_t ahi[4][4], bhi[4][2];
#pragma unroll
            for (int nf = 0; nf < 4; nf++)
                ldsm2(bhi[nf], bAddr + (uint32_t)(nf * 8 * 272 + ks * 32));
#pragma unroll
            for (int mf = 0; mf < 4; mf++)
                ldsm4(ahi[mf], aAddr + (uint32_t)(mf * 16 * 272 + ks * 32));
#pragma unroll
            for (int mf = 0; mf < 4; mf++)
#pragma unroll
                for (int nf = 0; nf < 4; nf++) mma_bf16(c[mf][nf], ahi[mf], bhi[nf]);
        }
        if (pan + 1 < panels) __syncthreads();
    }

    // ---- EPI4: hoist plane pointer + scale computation (depends only on nf) ----
    bf16* pl4[4];
    float qs4[4];
    if (EPI == 4) {
#pragma unroll
        for (int nf = 0; nf < 4; nf++) {
            int col = n0 + wn * 32 + nf * 8 + (lane & 3) * 2;
            int sec = (col >= 360) ? 1 : 0;
            int rem = col - sec * 360;
            int part = rem / 120;
            int within = rem % 120;
            int hh = within / 20, cc = within % 20;
            qs4[nf] = (part == 0) ? 0.22360679774997896f : 1.f;
            pl4[nf] = (bf16*)Cout + ((size_t)((sec * 3 + part) * 6 + hh)) * (TOKENS * 20) + cc;
        }
    }

#pragma unroll
    for (int mf = 0; mf < 4; mf++) {
        int row = row0 + wm * 64 + mf * 16 + (lane >> 2);
#pragma unroll
        for (int half = 0; half < 2; half++) {
            int r = row + half * 8;
            size_t obase = 0;
            const float* rbase = nullptr;
            if (EPI == 1) {
                int bwin = r >> 8, tt = r & 255;
                int ww = bwin & 7, wh = (bwin >> 3) & 7, wd = (bwin >> 6) & 1, wnn = bwin >> 7;
                int iw = tt & 7, ih = (tt >> 3) & 7, id = (tt >> 6) & 1, inn = tt >> 7;
                int n_ = wnn * 2 + inn, d_ = wd * 2 + id, h_ = wh * 8 + ih, w_ = ww * 8 + iw;
                int gidx = ((n_ * 4 + d_) * 64 + h_) * 64 + w_;
                obase = (size_t)gidx * 120;
                rbase = resid + obase;
            } else if (EPI == 0 || EPI == 2) {
                obase = (size_t)r * ldo;
                if (EPI == 2) rbase = resid + obase;
            }
#pragma unroll
            for (int nf = 0; nf < 4; nf++) {
                int col = n0 + wn * 32 + nf * 8 + (lane & 3) * 2;
                if (col >= N) continue;
                float2 bv = *(const float2*)&bias[col];
                float vx = c[mf][nf][half * 2 + 0] + bv.x;
                float vy = c[mf][nf][half * 2 + 1] + bv.y;
                if (EPI == 0) {
                    float2 v = {vx, vy};
                    *(float2*)&Cout[obase + col_off + col] = v;
                } else if (EPI == 3) {
                    float ge = 0.5f * vx * (1.f + erff(vx * 0.70710678118654752f));
                    ((bf16*)Cout)[(size_t)r * 240 + (col >> 1)] = __float2bfloat16(ge * vy);
                } else if (EPI == 4) {
                    *(uint32_t*)(pl4[nf] + (size_t)r * 20) = bf16pair(vx * qs4[nf], vy * qs4[nf]);
                } else {
                    float2 rv = *(const float2*)&rbase[col];
                    float2 v = {rv.x + vx, rv.y + vy};
                    *(float2*)&Cout[obase + col] = v;
                }
            }
        }
    }
}

// ---------------- HMMA attention (self+mutual in one launch via blockIdx.z) ----------------
// qkv in head-major planes [36][M][20] bf16: plane=(sec*3+part)*6+h. Staging fully coalesced.
// z=0: self (all 256 keys, out cols 120+h*20)
// z=1: mutual: warps 0-3 = q1 vs k2/v2 (kb 2-3), warps 4-7 = q2 vs k1/v1 (kb 0-1);
//      out row = qrow^128, out cols h*20.
#define ATTN_SMEM 61440

__global__ void __launch_bounds__(256, 2) attn_mma(
    const bf16* __restrict__ qkv, bf16* __restrict__ ohi)
{
    extern __shared__ char asmem[];
    uint32_t sbase = smem_u32(asmem);
    uint32_t Kbase = sbase + 20480;
    uint32_t Vbase = sbase + 40960;
    int h = blockIdx.y;
    int mutual = blockIdx.z;
    int base = blockIdx.x * 256;
    int tid = threadIdx.x;
    int lane = tid & 31, wid = tid >> 5;

    // zero full smem (pad cols 20..31 of every row must be 0)
    for (uint32_t off = (uint32_t)tid * 16; off < 61440; off += 256 * 16)
        zero16(sbase + off);
    __syncthreads();

    // coalesced staging: each plane slice [base..base+256) x 20 bf16 is contiguous (2560 u32)
    const uint32_t* Q32 = (const uint32_t*)(qkv + ((size_t)(mutual * 18 + h)) * (TOKENS * 20) + (size_t)base * 20);
    const uint32_t* K32 = (const uint32_t*)(qkv + ((size_t)(mutual * 18 + 6 + h)) * (TOKENS * 20) + (size_t)base * 20);
    const uint32_t* V32 = (const uint32_t*)(qkv + ((size_t)(mutual * 18 + 12 + h)) * (TOKENS * 20) + (size_t)base * 20);
#pragma unroll
    for (int idx = tid; idx < 2560; idx += 256) {
        int row = idx / 10, cp = idx % 10;
        uint32_t off = (uint32_t)(row * 80 + cp * 4);
        *(uint32_t*)(asmem + off) = Q32[idx];
        *(uint32_t*)(asmem + 20480 + off) = K32[idx];
        *(uint32_t*)(asmem + 40960 + off) = V32[idx];
    }
    __syncthreads();

    // Q fragments (loop-invariant)
    uint32_t aQ = sbase + (uint32_t)((wid * 32 + (lane & 15)) * 80 + ((lane >> 4) << 4));
    uint32_t aq[2][2][4];
#pragma unroll
    for (int mf = 0; mf < 2; mf++)
#pragma unroll
        for (int ks = 0; ks < 2; ks++)
            ldsm4(aq[mf][ks], aQ + (uint32_t)(mf * 16 * 80 + ks * 32));

    uint32_t aK = Kbase + (uint32_t)((lane & 7) * 80 + (lane & 8) * 2);
    uint32_t aV = Vbase + (uint32_t)((lane & 15) * 80);

    float l[4], o[2][3][4];
#pragma unroll
    for (int s = 0; s < 4; s++) l[s] = 0.f;
#pragma unroll
    for (int mf = 0; mf < 2; mf++)
#pragma unroll
        for (int nf = 0; nf < 3; nf++)
#pragma unroll
            for (int q = 0; q < 4; q++) o[mf][nf][q] = 0.f;

    int kb0 = mutual ? ((wid < 4) ? 2 : 0) : 0;
    int nkb = mutual ? 2 : 4;

    for (int kbi = 0; kbi < nkb; kbi++) {
        int kb = kb0 + kbi;
        float c[2][8][4];
#pragma unroll
        for (int mf = 0; mf < 2; mf++)
#pragma unroll
            for (int nf = 0; nf < 8; nf++)
#pragma unroll
                for (int q = 0; q < 4; q++) c[mf][nf][q] = 0.f;

        // S = Q K^T for 64 keys
#pragma unroll
        for (int nf = 0; nf < 8; nf++) {
            uint32_t b0[2], b1[2];
            uint32_t ka = aK + (uint32_t)((kb * 64 + nf * 8) * 80);
            ldsm2(b0, ka);
            ldsm2(b1, ka + 32);
#pragma unroll
            for (int mf = 0; mf < 2; mf++) {
                mma_bf16(c[mf][nf], aq[mf][0], b0);
                mma_bf16(c[mf][nf], aq[mf][1], b1);
            }
        }
        // exp (scores are small: no max subtraction needed) + row-sum
#pragma unroll
        for (int mf = 0; mf < 2; mf++)
#pragma unroll
            for (int hi = 0; hi < 2; hi++) {
                int s = mf * 2 + hi;
                float ls = 0.f;
#pragma unroll
                for (int nf = 0; nf < 8; nf++) {
                    float p0 = __expf(c[mf][nf][hi * 2]);
                    float p1 = __expf(c[mf][nf][hi * 2 + 1]);
                    c[mf][nf][hi * 2] = p0; c[mf][nf][hi * 2 + 1] = p1;
                    ls += p0 + p1;
                }
                ls += __shfl_xor_sync(0xffffffffu, ls, 1);
                ls += __shfl_xor_sync(0xffffffffu, ls, 2);
                l[s] += ls;
            }
        // PV: P(32x64) * V(64x24), V B-fragments via trans-ldmatrix
#pragma unroll
        for (int ks = 0; ks < 4; ks++) {
            uint32_t a[2][4];
#pragma unroll
            for (int mf = 0; mf < 2; mf++) {
                a[mf][0] = bf16pair(c[mf][2 * ks][0],     c[mf][2 * ks][1]);
                a[mf][1] = bf16pair(c[mf][2 * ks][2],     c[mf][2 * ks][3]);
                a[mf][2] = bf16pair(c[mf][2 * ks + 1][0], c[mf][2 * ks + 1][1]);
                a[mf][3] = bf16pair(c[mf][2 * ks + 1][2], c[mf][2 * ks + 1][3]);
            }
            uint32_t vrow = aV + (uint32_t)((kb * 64 + ks * 16) * 80);
#pragma unroll
            for (int nf = 0; nf < 3; nf++) {
                uint32_t vb[2];
                ldsm2_trans(vb, vrow + (uint32_t)(nf * 16));
#pragma unroll
                for (int mf = 0; mf < 2; mf++)
                    mma_bf16(o[mf][nf], a[mf], vb);
            }
        }
    }
    // normalize + write bf16 (cols 20-23 are pad)
    int colbase = mutual ? h * 20 : 120 + h * 20;
#pragma unroll
    for (int mf = 0; mf < 2; mf++)
#pragma unroll
        for (int hi = 0; hi < 2; hi++) {
            int s = mf * 2 + hi;
            float inv = 1.f / l[s];
            int qrow = wid * 32 + mf * 16 + (lane >> 2) + hi * 8;
            int orow = mutual ? (qrow ^ 128) : qrow;
            size_t ob = (size_t)(base + orow) * 240 + colbase;
#pragma unroll
            for (int nf = 0; nf < 3; nf++) {
                int col = nf * 8 + (lane & 3) * 2;
                if (col < 20) {
                    *(uint32_t*)(ohi + ob + col) =
                        bf16pair(o[mf][nf][hi * 2] * inv, o[mf][nf][hi * 2 + 1] * inv);
                }
            }
        }
}

extern "C" void kernel_launch(void* const* d_in, const int* in_sizes, int n_in,
                              void* d_out, int out_size)
{
    const float* x          = (const float*)d_in[0];
    const float* norm1_w    = (const float*)d_in[1];
    const float* norm1_b    = (const float*)d_in[2];
    const float* qkv_self_w = (const float*)d_in[3];
    const float* qkv_self_b = (const float*)d_in[4];
    const float* qkv_mut_w  = (const float*)d_in[5];
    const float* qkv_mut_b  = (const float*)d_in[6];
    const float* proj_w     = (const float*)d_in[7];
    const float* proj_b     = (const float*)d_in[8];
    const float* norm2_w    = (const float*)d_in[9];
    const float* norm2_b    = (const float*)d_in[10];
    const float* fc11_w     = (const float*)d_in[11];
    const float* fc11_b     = (const float*)d_in[12];
    const float* fc12_w     = (const float*)d_in[13];
    const float* fc12_b     = (const float*)d_in[14];
    const float* fc2_w      = (const float*)d_in[15];
    const float* fc2_b      = (const float*)d_in[16];

    float *bufA, *xres, *biasp;
    bf16 *lnhi, *athi, *whi;
    cudaGetSymbolAddress((void**)&bufA, g_bufA);
    cudaGetSymbolAddress((void**)&xres, g_xres);
    cudaGetSymbolAddress((void**)&lnhi, g_ln_hi);
    cudaGetSymbolAddress((void**)&athi, g_at_hi);
    cudaGetSymbolAddress((void**)&whi, g_w_hi);
    cudaGetSymbolAddress((void**)&biasp, g_bias);

    cudaFuncSetAttribute(mma_gemm<1>, cudaFuncAttributeMaxDynamicSharedMemorySize, GEMM_SMEM);
    cudaFuncSetAttribute(mma_gemm<2>, cudaFuncAttributeMaxDynamicSharedMemorySize, GEMM_SMEM);
    cudaFuncSetAttribute(mma_gemm<3>, cudaFuncAttributeMaxDynamicSharedMemorySize, GEMM_SMEM);
    cudaFuncSetAttribute(mma_gemm<4>, cudaFuncAttributeMaxDynamicSharedMemorySize, GEMM_SMEM);
    cudaFuncSetAttribute(attn_mma, cudaFuncAttributeMaxDynamicSharedMemorySize, ATTN_SMEM);

    const int M = TOKENS;
    const int MT = M / 128;

    // 0) weight/bias prep (mlp rows interleaved for gate fusion)
    prep_weights<<<(201600 + 1200 + 255) / 256, 256>>>(
        qkv_self_w, qkv_mut_w, proj_w, fc11_w, fc12_w, fc2_w,
        qkv_self_b, qkv_mut_b, fc11_b, fc12_b);

    // 1) LN1 + window partition -> bf16
    ln_kernel<<<M / 8, 256>>>(x, norm1_w, norm1_b, lnhi, 1);

    // 2) combined qkv GEMM (N=720) -> bufA as bf16 head-major planes, Q pre-scaled
    mma_gemm<4><<<dim3(MT, 6), 256, GEMM_SMEM>>>(lnhi, whi, biasp, bufA, nullptr, 720, 120, 720, 0);

    // 3) attention (self z=0, mutual z=1) -> athi bf16 [M,240]
    attn_mma<<<dim3(512, 6, 2), 256, ATTN_SMEM>>>((const bf16*)bufA, athi);

    // 4) proj GEMM + window reverse + residual -> xres
    mma_gemm<1><<<dim3(MT, 1), 256, GEMM_SMEM>>>(athi, whi + 86400, proj_b, xres, x, 120, 240, 120, 0);

    // 5) LN2 -> bf16
    ln_kernel<<<M / 8, 256>>>(xres, norm2_w, norm2_b, lnhi, 0);

    // 6) MLP GEMM with fused GEGLU (N=480 interleaved) -> athi bf16 [M,240]
    mma_gemm<3><<<dim3(MT, 4), 256, GEMM_SMEM>>>(lnhi, whi + 115200, biasp + 720,
                                                 (float*)athi, nullptr, 480, 120, 240, 0);

    // 7) fc2 GEMM + residual -> d_out
    mma_gemm<2><<<dim3(MT, 1), 256, GEMM_SMEM>>>(athi, whi + 172800, fc2_b, (float*)d_out, xres, 120, 240, 120, 0);
}